// round 12
// baseline (speedup 1.0000x reference)
#include <cuda_runtime.h>
#include <cuda_bf16.h>
#include <cstdint>

// Problem constants (fixed by the dataset)
#define NV 8192
#define DV 128
#define TILE 128
#define GT (NV / TILE)   // 64 tiles per dim

// -------- device scratch (no allocs allowed) --------
__device__ __nv_bfloat16 g_wbf[(size_t)NV * DV];   // bf16 weights (2 MB, L2-resident)
__device__ float g_sq[NV];                          // fp32 row squared norms
__device__ float g_part[GT * GT];                   // per-tile partial sums

// ============================================================
// Helpers (portable PTX only: compute_103 virtual target)
// ============================================================
static __device__ __forceinline__ uint32_t smem_u32(const void* p) {
    uint32_t a;
    asm("{ .reg .u64 t; cvta.to.shared.u64 t, %1; cvt.u32.u64 %0, t; }"
        : "=r"(a) : "l"(p));
    return a;
}
static __device__ __forceinline__ float fsqrt_fast(float x) {
    float r; asm("sqrt.approx.f32 %0, %1;" : "=f"(r) : "f"(x)); return r;
}
static __device__ __forceinline__ void ldsm_x4(uint32_t& r0, uint32_t& r1,
                                               uint32_t& r2, uint32_t& r3,
                                               uint32_t addr) {
    asm volatile("ldmatrix.sync.aligned.m8n8.x4.shared.b16 {%0,%1,%2,%3}, [%4];"
                 : "=r"(r0), "=r"(r1), "=r"(r2), "=r"(r3) : "r"(addr));
}
static __device__ __forceinline__ void ldsm_x2(uint32_t& r0, uint32_t& r1,
                                               uint32_t addr) {
    asm volatile("ldmatrix.sync.aligned.m8n8.x2.shared.b16 {%0,%1}, [%2];"
                 : "=r"(r0), "=r"(r1) : "r"(addr));
}
static __device__ __forceinline__ void mma16816(float* d, const uint32_t* a,
                                                const uint32_t* b) {
    asm volatile(
        "mma.sync.aligned.m16n8k16.row.col.f32.bf16.bf16.f32 "
        "{%0,%1,%2,%3}, {%4,%5,%6,%7}, {%8,%9}, {%0,%1,%2,%3};"
        : "+f"(d[0]), "+f"(d[1]), "+f"(d[2]), "+f"(d[3])
        : "r"(a[0]), "r"(a[1]), "r"(a[2]), "r"(a[3]), "r"(b[0]), "r"(b[1]));
}
static __device__ __forceinline__ void cp16(uint32_t dst, const void* src) {
    asm volatile("cp.async.cg.shared.global [%0], [%1], 16;"
                 :: "r"(dst), "l"(src));
}
#define CP_COMMIT() asm volatile("cp.async.commit_group;" ::: "memory")
#define CP_WAIT(n)  asm volatile("cp.async.wait_group %0;" :: "n"(n) : "memory")

// W K=32 slice tile: 128 rows x 32 bf16 = 64 B/row = 8 KB.
// Row r, 16B chunk c in 0..3; physical chunk = c ^ ((r>>1)&3)
// -> every ldmatrix 8-row group hits 8 distinct 16B bank-granules.
static __device__ __forceinline__ uint32_t w_off32(int row, int c) {
    return (uint32_t)(row * 64 + ((c ^ ((row >> 1) & 3)) << 4));
}

// ============================================================
// Kernel 1: fp32 weights -> bf16 buffer + squared norms
// ============================================================
__global__ void prep_kernel(const float* __restrict__ w) {
    int t = blockIdx.x * blockDim.x + threadIdx.x;
    int row = t >> 5;
    int lid = t & 31;
    if (row >= NV) return;
    float4 v = reinterpret_cast<const float4*>(w + (size_t)row * DV)[lid];
    __nv_bfloat162 p0 = __float22bfloat162_rn(make_float2(v.x, v.y));
    __nv_bfloat162 p1 = __float22bfloat162_rn(make_float2(v.z, v.w));
    uint2 pk;
    pk.x = *reinterpret_cast<uint32_t*>(&p0);
    pk.y = *reinterpret_cast<uint32_t*>(&p1);
    *reinterpret_cast<uint2*>(&g_wbf[(size_t)row * DV + lid * 4]) = pk;
    float s = v.x * v.x + v.y * v.y + v.z * v.z + v.w * v.w;
    #pragma unroll
    for (int o = 16; o; o >>= 1) s += __shfl_xor_sync(0xffffffffu, s, o);
    if (lid == 0) g_sq[row] = s;
}

// ============================================================
// SMEM map (static, exactly 48 KB):
//   [0,      8192)  Wm K-slice (8 KB)
//   [8192,  16384)  Wn K-slice (8 KB)
//   [16384, 32768)  A phase buffer 0 (8 KB direct + 8 KB transposed)
//   [32768, 49152)  A phase buffer 1
// Phase s (0..7): m-rows { s*8+q } u { 64+s*8+q }, q=0..7 (16 rows).
//   direct: dbuf[16][128] floats, row rl rotated by rl*8 floats.
//   trans:  tbuf[128][16] floats, 16B chunk g at (g ^ (j&3)).
// ============================================================
static constexpr int SM_A = 16384;

// Issue cp.async for phase s into buffer (s&1). All 256 threads participate.
static __device__ __forceinline__ void issue_phase(
    int s, int tid, uint32_t smem_base, const float* __restrict__ A,
    int m0, int n0) {
    const uint32_t bufb = smem_base + SM_A + ((s & 1) << 14);
    // direct: 16 rows x 32 chunks = 512 chunks
    #pragma unroll
    for (int it = 0; it < 2; it++) {
        int ci = tid + it * 256;            // 0..511
        int rl = ci >> 5;                   // 0..15
        int c16 = ci & 31;
        int mrow = m0 + (rl < 8 ? s * 8 + rl : 64 + s * 8 + (rl - 8));
        const float* src = A + (size_t)mrow * NV + n0 + c16 * 4;
        uint32_t dst = bufb + rl * 512 + (uint32_t)((c16 * 16 + rl * 32) & 511);
        cp16(dst, src);
    }
    // transposed: 128 n-rows x 4 chunks = 512 chunks
    #pragma unroll
    for (int it = 0; it < 2; it++) {
        int ci = tid + it * 256;
        int j = ci >> 2;                    // 0..127
        int g = ci & 3;
        int mcol = m0 + (g >> 1) * 64 + s * 8 + (g & 1) * 4;
        const float* src = A + (size_t)(n0 + j) * NV + mcol;
        uint32_t dst = bufb + 8192 + j * 64 + (uint32_t)((g ^ (j & 3)) << 4);
        cp16(dst, src);
    }
    CP_COMMIT();
}

// ============================================================
// Kernel 2: SYMMETRIC tiles (ti<=tj), mma.sync Gram, cp.async A pipeline.
// 8 warps 2(m) x 4(n), warp tile 64x32; K=128 in four K=32 SMEM slices.
// ============================================================
__global__ __launch_bounds__(256, 2)
void tile_kernel(const float* __restrict__ A) {
    const int tj = blockIdx.x;
    const int ti = blockIdx.y;
    if (ti > tj) return;
    const bool diag = (ti == tj);

    __shared__ __align__(16) char smem[49152];
    const uint32_t sb = smem_u32(smem);
    char* s_wm = smem;
    char* s_wn = smem + 8192;

    const int tid = threadIdx.x;
    const int wid = tid >> 5;
    const int lid = tid & 31;
    const int wm = wid >> 2;          // 0..1
    const int wn = wid & 3;           // 0..3
    const int m0 = ti * TILE;
    const int n0 = tj * TILE;
    const int q  = lid >> 2;          // 0..7 fragment row group

    // start A pipeline: phases 0 and 1 stream during the MMA mainloop
    issue_phase(0, tid, sb, A, m0, n0);
    issue_phase(1, tid, sb, A, m0, n0);

    // preload column squared norms for this thread's 8 n positions
    float sn0r[4], sn1r[4];
    #pragma unroll
    for (int ni = 0; ni < 4; ni++) {
        int c0 = wn * 32 + ni * 8 + 2 * (lid & 3);
        sn0r[ni] = __ldg(&g_sq[n0 + c0]);
        sn1r[ni] = __ldg(&g_sq[n0 + c0 + 1]);
    }

    float acc[4][4][4];
    #pragma unroll
    for (int mi = 0; mi < 4; mi++)
        #pragma unroll
        for (int ni = 0; ni < 4; ni++)
            #pragma unroll
            for (int e = 0; e < 4; e++) acc[mi][ni][e] = 0.0f;

    // --- mainloop: four K=32 slices ---
    #pragma unroll
    for (int kt = 0; kt < 4; kt++) {
        #pragma unroll
        for (int it = 0; it < 2; it++) {
            int i = tid + it * 256;          // 0..511
            int row = i >> 2, c = i & 3;
            const size_t gk = (size_t)kt * 32 + c * 8;
            uint4 vm = *reinterpret_cast<const uint4*>(
                &g_wbf[(size_t)(m0 + row) * DV + gk]);
            *reinterpret_cast<uint4*>(s_wm + w_off32(row, c)) = vm;
            uint4 vn = *reinterpret_cast<const uint4*>(
                &g_wbf[(size_t)(n0 + row) * DV + gk]);
            *reinterpret_cast<uint4*>(s_wn + w_off32(row, c)) = vn;
        }
        __syncthreads();

        #pragma unroll
        for (int ks = 0; ks < 2; ks++) {
            uint32_t af[4][4], bf[4][2];
            #pragma unroll
            for (int mi = 0; mi < 4; mi++) {
                int row = wm * 64 + mi * 16 + (lid & 15);
                int ch  = ks * 2 + (lid >> 4);
                ldsm_x4(af[mi][0], af[mi][1], af[mi][2], af[mi][3],
                        sb + w_off32(row, ch));
            }
            #pragma unroll
            for (int ni = 0; ni < 4; ni++) {
                int row = wn * 32 + ni * 8 + (lid & 7);
                int ch  = ks * 2 + ((lid >> 3) & 1);
                ldsm_x2(bf[ni][0], bf[ni][1], sb + 8192 + w_off32(row, ch));
            }
            #pragma unroll
            for (int mi = 0; mi < 4; mi++)
                #pragma unroll
                for (int ni = 0; ni < 4; ni++)
                    mma16816(acc[mi][ni], af[mi], bf[ni]);
        }
        if (kt < 3) __syncthreads();   // protect W smem before next slice's stores
    }

    // --- epilogue: 8 pipelined phases ---
    float asum = 0.0f;
    #pragma unroll
    for (int s = 0; s < 8; s++) {
        if (s == 7) { CP_WAIT(0); } else { CP_WAIT(1); }
        __syncthreads();

        const int mi = s >> 1;
        const int e0 = (s & 1) * 2;          // acc element pair for this row half
        const char* ab = smem + SM_A + ((s & 1) << 14);
        const float* dbuf = reinterpret_cast<const float*>(ab);
        const float* tbuf = reinterpret_cast<const float*>(ab + 8192);
        const int rl = wm * 8 + q;           // direct-buffer row 0..15
        const int g  = wm * 2 + (q >> 2);    // transposed chunk class
        const float sqm = __ldg(&g_sq[m0 + wm * 64 + s * 8 + q]);

        #pragma unroll
        for (int ni = 0; ni < 4; ni++) {
            const int c0 = wn * 32 + ni * 8 + 2 * (lid & 3);
            const int pc = (c0 + rl * 8) & 127;
            float2 av = *reinterpret_cast<const float2*>(&dbuf[rl * 128 + pc]);
            float w0 = av.x, w1 = av.y;
            if (!diag) {
                w0 += tbuf[c0 * 16 + ((g ^ (c0 & 3)) << 2) + (q & 3)];
                w1 += tbuf[(c0 + 1) * 16 + ((g ^ ((c0 + 1) & 3)) << 2) + (q & 3)];
            }
            float d0 = fmaxf(sqm + sn0r[ni] - 2.0f * acc[mi][ni][e0],     0.0f);
            float d1 = fmaxf(sqm + sn1r[ni] - 2.0f * acc[mi][ni][e0 + 1], 0.0f);
            asum = fmaf(w0, fsqrt_fast(d0), asum);
            asum = fmaf(w1, fsqrt_fast(d1), asum);
        }

        __syncthreads();                     // all reads of buffer (s&1) done
        if (s < 6) issue_phase(s + 2, tid, sb, A, m0, n0);
    }

    // --- deterministic reduction: warp -> smem -> thread 0 ---
    #pragma unroll
    for (int o = 16; o; o >>= 1) asum += __shfl_xor_sync(0xffffffffu, asum, o);
    __syncthreads();                          // A buffers fully consumed
    float* sred = reinterpret_cast<float*>(smem + SM_A);
    if (lid == 0) sred[wid] = asum;
    __syncthreads();
    if (tid == 0) {
        float s = ((sred[0] + sred[1]) + (sred[2] + sred[3]))
                + ((sred[4] + sred[5]) + (sred[6] + sred[7]));
        g_part[ti * GT + tj] = s;
    }
}

// ============================================================
// Kernel 3: deterministic final reduction (upper-triangle partials only)
// ============================================================
__global__ void reduce_kernel(float* __restrict__ out) {
    __shared__ float sh[256];
    float s = 0.0f;
    for (int i = threadIdx.x; i < GT * GT; i += 256) {
        int ti = i / GT, tj = i % GT;
        if (ti <= tj) s += g_part[i];
    }
    sh[threadIdx.x] = s;
    __syncthreads();
    #pragma unroll
    for (int o = 128; o; o >>= 1) {
        if (threadIdx.x < o) sh[threadIdx.x] += sh[threadIdx.x + o];
        __syncthreads();
    }
    if (threadIdx.x == 0) out[0] = sh[0];
}

// ============================================================
// kernel_launch — plain launches only, no attribute calls, no opt-ins
// ============================================================
extern "C" void kernel_launch(void* const* d_in, const int* in_sizes, int n_in,
                              void* d_out, int out_size) {
    const float* A = (const float*)d_in[0];       // [N, N]
    const float* W = (const float*)d_in[1];       // [N, D]
    float* out = (float*)d_out;                   // [1 + N*D]: result then weights

    // weights pass-through (exact copy), overlaps with compute
    if (out_size >= 1 + NV * DV) {
        cudaMemcpyAsync(out + 1, W, (size_t)NV * DV * sizeof(float),
                        cudaMemcpyDeviceToDevice, 0);
    }

    prep_kernel<<<(NV * 32) / 256, 256>>>(W);

    dim3 grid(GT, GT);
    tile_kernel<<<grid, 256>>>(A);

    reduce_kernel<<<1, 256>>>(out);
}

// round 13
// speedup vs baseline: 1.0475x; 1.0475x over previous
#include <cuda_runtime.h>
#include <cuda_bf16.h>
#include <cstdint>

// Problem constants (fixed by the dataset)
#define NV 8192
#define DV 128
#define TILE 128
#define GT (NV / TILE)   // 64 tiles per dim

// -------- device scratch (no allocs allowed) --------
__device__ __nv_bfloat16 g_wbf[(size_t)NV * DV];   // bf16 weights (2 MB, L2-resident)
__device__ float g_sq[NV];                          // fp32 row squared norms
__device__ float g_part[GT * GT];                   // per-tile partial sums

// ============================================================
// Helpers (portable PTX only: compute_103 virtual target)
// ============================================================
static __device__ __forceinline__ uint32_t smem_u32(const void* p) {
    uint32_t a;
    asm("{ .reg .u64 t; cvta.to.shared.u64 t, %1; cvt.u32.u64 %0, t; }"
        : "=r"(a) : "l"(p));
    return a;
}
static __device__ __forceinline__ float fsqrt_fast(float x) {
    float r; asm("sqrt.approx.f32 %0, %1;" : "=f"(r) : "f"(x)); return r;
}
static __device__ __forceinline__ void ldsm_x4(uint32_t& r0, uint32_t& r1,
                                               uint32_t& r2, uint32_t& r3,
                                               uint32_t addr) {
    asm volatile("ldmatrix.sync.aligned.m8n8.x4.shared.b16 {%0,%1,%2,%3}, [%4];"
                 : "=r"(r0), "=r"(r1), "=r"(r2), "=r"(r3) : "r"(addr));
}
static __device__ __forceinline__ void ldsm_x2(uint32_t& r0, uint32_t& r1,
                                               uint32_t addr) {
    asm volatile("ldmatrix.sync.aligned.m8n8.x2.shared.b16 {%0,%1}, [%2];"
                 : "=r"(r0), "=r"(r1) : "r"(addr));
}
static __device__ __forceinline__ void mma16816(float* d, const uint32_t* a,
                                                const uint32_t* b) {
    asm volatile(
        "mma.sync.aligned.m16n8k16.row.col.f32.bf16.bf16.f32 "
        "{%0,%1,%2,%3}, {%4,%5,%6,%7}, {%8,%9}, {%0,%1,%2,%3};"
        : "+f"(d[0]), "+f"(d[1]), "+f"(d[2]), "+f"(d[3])
        : "r"(a[0]), "r"(a[1]), "r"(a[2]), "r"(a[3]), "r"(b[0]), "r"(b[1]));
}
static __device__ __forceinline__ void cp16(uint32_t dst, const void* src) {
    asm volatile("cp.async.cg.shared.global [%0], [%1], 16;"
                 :: "r"(dst), "l"(src));
}
#define CP_COMMIT() asm volatile("cp.async.commit_group;" ::: "memory")
#define CP_WAIT(n)  asm volatile("cp.async.wait_group %0;" :: "n"(n) : "memory")

// W K=32 slice tile: 128 rows x 32 bf16 = 64 B/row = 8 KB.
// Row r, 16B chunk c in 0..3; physical chunk = c ^ ((r>>1)&3).
static __device__ __forceinline__ uint32_t w_off32(int row, int c) {
    return (uint32_t)(row * 64 + ((c ^ ((row >> 1) & 3)) << 4));
}

// ============================================================
// Kernel 1: fp32 weights -> bf16 buffer + squared norms
// ============================================================
__global__ void prep_kernel(const float* __restrict__ w) {
    int t = blockIdx.x * blockDim.x + threadIdx.x;
    int row = t >> 5;
    int lid = t & 31;
    if (row >= NV) return;
    float4 v = reinterpret_cast<const float4*>(w + (size_t)row * DV)[lid];
    __nv_bfloat162 p0 = __float22bfloat162_rn(make_float2(v.x, v.y));
    __nv_bfloat162 p1 = __float22bfloat162_rn(make_float2(v.z, v.w));
    uint2 pk;
    pk.x = *reinterpret_cast<uint32_t*>(&p0);
    pk.y = *reinterpret_cast<uint32_t*>(&p1);
    *reinterpret_cast<uint2*>(&g_wbf[(size_t)row * DV + lid * 4]) = pk;
    float s = v.x * v.x + v.y * v.y + v.z * v.z + v.w * v.w;
    #pragma unroll
    for (int o = 16; o; o >>= 1) s += __shfl_xor_sync(0xffffffffu, s, o);
    if (lid == 0) g_sq[row] = s;
}

// ============================================================
// SMEM map (static, exactly 48 KB):
//   [0,      8192)  Wm K-slice (8 KB)
//   [8192,  16384)  Wn K-slice (8 KB)
//   [16384, 49152)  A region: warp w owns [16384 + w*4096, +4096):
//                   two 2 KB phase buffers (double buffered).
// Per-warp phase p (0..7) covers warp fragment rows wm*64 + p*8 + 0..7:
//   direct: 8 rows x 32 floats (128 B/row), 16B chunk c at (c + r) & 7.
//   trans:  32 n-rows x 8 floats (32 B/row), 16B chunk g at g ^ (j & 1).
// ============================================================
static constexpr int SM_A = 16384;

static __device__ __forceinline__ void issue_phase_w(
    int p, int lane, uint32_t bufb, const float* __restrict__ A,
    int m0, int n0, int wm, int wn) {
    // direct: 64 x 16B chunks (8 rows x 8 chunks)
    #pragma unroll
    for (int it = 0; it < 2; it++) {
        int id = lane + it * 32;
        int r = id >> 3, c = id & 7;
        const float* src = A + (size_t)(m0 + wm * 64 + p * 8 + r) * NV
                             + (n0 + wn * 32 + c * 4);
        cp16(bufb + r * 128 + (((c + r) & 7) << 4), src);
    }
    // transposed: 64 x 16B chunks (32 n-rows x 2 chunks)
    #pragma unroll
    for (int it = 0; it < 2; it++) {
        int id = lane + it * 32;
        int j = id >> 1, g = id & 1;
        const float* src = A + (size_t)(n0 + wn * 32 + j) * NV
                             + (m0 + wm * 64 + p * 8 + g * 4);
        cp16(bufb + 1024 + j * 32 + ((g ^ (j & 1)) << 4), src);
    }
    CP_COMMIT();
}

// ============================================================
// Kernel 2: SYMMETRIC tiles (ti<=tj), mma.sync Gram, warp-autonomous
// cp.async A pipeline (no block barriers in the epilogue).
// 8 warps 2(m) x 4(n), warp tile 64x32; K=128 in four K=32 SMEM slices.
// ============================================================
__global__ __launch_bounds__(256, 2)
void tile_kernel(const float* __restrict__ A) {
    const int tj = blockIdx.x;
    const int ti = blockIdx.y;
    if (ti > tj) return;
    const bool diag = (ti == tj);

    __shared__ __align__(16) char smem[49152];
    const uint32_t sb = smem_u32(smem);
    char* s_wm = smem;
    char* s_wn = smem + 8192;

    const int tid = threadIdx.x;
    const int wid = tid >> 5;
    const int lid = tid & 31;
    const int wm = wid >> 2;          // 0..1
    const int wn = wid & 3;           // 0..3
    const int m0 = ti * TILE;
    const int n0 = tj * TILE;
    const int q  = lid >> 2;          // 0..7 fragment row group
    const int t4 = lid & 3;           // fragment col group

    const uint32_t mybase = sb + SM_A + wid * 4096;

    // start this warp's A pipeline before the mainloop
    issue_phase_w(0, lid, mybase,        A, m0, n0, wm, wn);
    issue_phase_w(1, lid, mybase + 2048, A, m0, n0, wm, wn);

    // preload column squared norms for this thread's 8 n positions
    float sn0r[4], sn1r[4];
    #pragma unroll
    for (int ni = 0; ni < 4; ni++) {
        int c0 = wn * 32 + ni * 8 + 2 * t4;
        sn0r[ni] = __ldg(&g_sq[n0 + c0]);
        sn1r[ni] = __ldg(&g_sq[n0 + c0 + 1]);
    }

    float acc[4][4][4];
    #pragma unroll
    for (int mi = 0; mi < 4; mi++)
        #pragma unroll
        for (int ni = 0; ni < 4; ni++)
            #pragma unroll
            for (int e = 0; e < 4; e++) acc[mi][ni][e] = 0.0f;

    // --- mainloop: four K=32 slices ---
    #pragma unroll
    for (int kt = 0; kt < 4; kt++) {
        #pragma unroll
        for (int it = 0; it < 2; it++) {
            int i = tid + it * 256;          // 0..511
            int row = i >> 2, c = i & 3;
            const size_t gk = (size_t)kt * 32 + c * 8;
            uint4 vm = *reinterpret_cast<const uint4*>(
                &g_wbf[(size_t)(m0 + row) * DV + gk]);
            *reinterpret_cast<uint4*>(s_wm + w_off32(row, c)) = vm;
            uint4 vn = *reinterpret_cast<const uint4*>(
                &g_wbf[(size_t)(n0 + row) * DV + gk]);
            *reinterpret_cast<uint4*>(s_wn + w_off32(row, c)) = vn;
        }
        __syncthreads();

        #pragma unroll
        for (int ks = 0; ks < 2; ks++) {
            uint32_t af[4][4], bf[4][2];
            #pragma unroll
            for (int mi = 0; mi < 4; mi++) {
                int row = wm * 64 + mi * 16 + (lid & 15);
                int ch  = ks * 2 + (lid >> 4);
                ldsm_x4(af[mi][0], af[mi][1], af[mi][2], af[mi][3],
                        sb + w_off32(row, ch));
            }
            #pragma unroll
            for (int ni = 0; ni < 4; ni++) {
                int row = wn * 32 + ni * 8 + (lid & 7);
                int ch  = ks * 2 + ((lid >> 3) & 1);
                ldsm_x2(bf[ni][0], bf[ni][1], sb + 8192 + w_off32(row, ch));
            }
            #pragma unroll
            for (int mi = 0; mi < 4; mi++)
                #pragma unroll
                for (int ni = 0; ni < 4; ni++)
                    mma16816(acc[mi][ni], af[mi], bf[ni]);
        }
        if (kt < 3) __syncthreads();   // protect W smem before next slice's stores
    }

    // --- epilogue: 8 warp-autonomous phases, warp-level sync only ---
    float asum = 0.0f;
    #pragma unroll
    for (int p = 0; p < 8; p++) {
        if (p < 7) { CP_WAIT(1); } else { CP_WAIT(0); }
        __syncwarp();

        const float* dbuf = reinterpret_cast<const float*>(
            smem + SM_A + wid * 4096 + (p & 1) * 2048);
        const float* tbuf = dbuf + 256;
        const int mi = p >> 1;
        const int e0 = (p & 1) * 2;
        const float sqm = __ldg(&g_sq[m0 + wm * 64 + p * 8 + q]);

        #pragma unroll
        for (int ni = 0; ni < 4; ni++) {
            const int x = ni * 8 + 2 * t4;               // warp-local col 0..31
            const int pc = ((x >> 2) + q) & 7;           // rotated 16B chunk
            float2 av = *reinterpret_cast<const float2*>(
                &dbuf[q * 32 + pc * 4 + (x & 3)]);
            float w0 = av.x, w1 = av.y;
            if (!diag) {
                w0 += tbuf[x * 8 + (((q >> 2) ^ 0) << 2) + (q & 3)];
                w1 += tbuf[(x + 1) * 8 + (((q >> 2) ^ 1) << 2) + (q & 3)];
            }
            float d0 = fmaxf(sqm + sn0r[ni] - 2.0f * acc[mi][ni][e0],     0.0f);
            float d1 = fmaxf(sqm + sn1r[ni] - 2.0f * acc[mi][ni][e0 + 1], 0.0f);
            asum = fmaf(w0, fsqrt_fast(d0), asum);
            asum = fmaf(w1, fsqrt_fast(d1), asum);
        }

        __syncwarp();                        // reads done before buffer reuse
        if (p < 6) issue_phase_w(p + 2, lid,
                                 sb + SM_A + wid * 4096 + (p & 1) * 2048,
                                 A, m0, n0, wm, wn);
    }

    // --- deterministic reduction: warp -> own smem slot -> thread 0 ---
    #pragma unroll
    for (int o = 16; o; o >>= 1) asum += __shfl_xor_sync(0xffffffffu, asum, o);
    if (lid == 0)
        *reinterpret_cast<float*>(smem + SM_A + wid * 4096) = asum;  // own region
    __syncthreads();
    if (tid == 0) {
        const float* r0 = reinterpret_cast<const float*>(smem + SM_A);
        float s = 0.0f;
        #pragma unroll
        for (int w = 0; w < 8; w++) s += r0[w * 1024];
        g_part[ti * GT + tj] = s;
    }
}

// ============================================================
// Kernel 3: deterministic final reduction (upper-triangle partials only)
// ============================================================
__global__ void reduce_kernel(float* __restrict__ out) {
    __shared__ float sh[256];
    float s = 0.0f;
    for (int i = threadIdx.x; i < GT * GT; i += 256) {
        int ti = i / GT, tj = i % GT;
        if (ti <= tj) s += g_part[i];
    }
    sh[threadIdx.x] = s;
    __syncthreads();
    #pragma unroll
    for (int o = 128; o; o >>= 1) {
        if (threadIdx.x < o) sh[threadIdx.x] += sh[threadIdx.x + o];
        __syncthreads();
    }
    if (threadIdx.x == 0) out[0] = sh[0];
}

// ============================================================
// kernel_launch — plain launches only, no attribute calls, no opt-ins
// ============================================================
extern "C" void kernel_launch(void* const* d_in, const int* in_sizes, int n_in,
                              void* d_out, int out_size) {
    const float* A = (const float*)d_in[0];       // [N, N]
    const float* W = (const float*)d_in[1];       // [N, D]
    float* out = (float*)d_out;                   // [1 + N*D]: result then weights

    // weights pass-through (exact copy), overlaps with compute
    if (out_size >= 1 + NV * DV) {
        cudaMemcpyAsync(out + 1, W, (size_t)NV * DV * sizeof(float),
                        cudaMemcpyDeviceToDevice, 0);
    }

    prep_kernel<<<(NV * 32) / 256, 256>>>(W);

    dim3 grid(GT, GT);
    tile_kernel<<<grid, 256>>>(A);

    reduce_kernel<<<1, 256>>>(out);
}